// round 16
// baseline (speedup 1.0000x reference)
#include <cuda_runtime.h>
#include <cuda_bf16.h>
#include <cstdint>

#define NPTS 12288
#define DIM 16
#define KSPLIT 6
#define QT_TILES 96                     // 12288/128 query tiles
#define TPB 256
#define KEYS_PER_SPLIT (NPTS / KSPLIT)  // 2048
#define KEYTILE 512
#define TILES (KEYS_PER_SPLIT / KEYTILE)// 4
#define SOP_BPTS 128                    // points per sop block
#define SOP_BLOCKS (NPTS / SOP_BPTS)    // 96

// ---- scratch (__device__ globals; no allocation allowed) ------------------
__device__ uint32_t g_kb[NPTS * 8];         // keys, bf16x2, unscaled
__device__ float g_se[KSPLIT][NPTS];        // exp-sum partials
__device__ float g_sw[KSPLIT][NPTS];        // exp*score-sum partials (log2-units)
__device__ float g_Mpart[SOP_BLOCKS][256];  // per-block SOP partials
__device__ unsigned int g_cnt = 0;          // last-block counter (self-resetting)

__device__ __forceinline__ float ex2_approx(float x) {
    float r; asm("ex2.approx.ftz.f32 %0, %1;" : "=f"(r) : "f"(x)); return r;
}
// fma-pipe 2^t: linear-mantissa bit trick (±2% ripple; 50/50 alternation
// with MUFU cancels the systematic part — proven rel_err ~8e-6 in R13).
__device__ __forceinline__ float bexp2(float t) {
    float f = fmaf(t, 8388608.0f, 1065353216.0f);   // t*2^23 + 127*2^23
    return __int_as_float((int)f);
}
__device__ __forceinline__ uint32_t bf2_u32(__nv_bfloat162 v) {
    return *reinterpret_cast<uint32_t*>(&v);
}

// ---------------------------------------------------------------------------
// Kernel 0: convert feats (f32) to the bf16 KEY array only (queries are
// converted in-kernel by attn). One float4 -> one uint2 per thread.
// ---------------------------------------------------------------------------
__global__ void convert_kernel(const float* __restrict__ feats) {
    const int i = blockIdx.x * 256 + threadIdx.x;   // float4 index, 0..49151
    float4 v = reinterpret_cast<const float4*>(feats)[i];
    uint2 kb = make_uint2(bf2_u32(__floats2bfloat162_rn(v.x, v.y)),
                          bf2_u32(__floats2bfloat162_rn(v.z, v.w)));
    reinterpret_cast<uint2*>(g_kb)[i] = kb;
}

// ---------------------------------------------------------------------------
// Kernel 1: tensor-core attention row stats via warp-level mma.sync.
// Identical to R15 except the epilogue exp is HYBRID: per MMA, 2 of the 4
// exps use MUFU ex2 and 2 use the fma-pipe bexp2 bit-trick, roles
// alternating with key-iteration parity (halves the binding MUFU load).
// Warp owns 16 queries; A frags from feats (f32 -> scaled bf16, once).
// 512-key smem tiles at 48B/key stride (conflict-free B loads).
// Identity: <ctx_q,f_q> = 4*ln2 * sw_q/se_q -> no ctx materialization.
// ---------------------------------------------------------------------------
__global__ void __launch_bounds__(TPB, 4) attn_mma_kernel(const float* __restrict__ feats) {
    __shared__ uint32_t sk[KEYTILE * 12];   // 24 KB, 48B per key (12 words)

    const int tid  = threadIdx.x;
    const int warp = tid >> 5;
    const int lane = tid & 31;
    const int g    = lane >> 2;             // 0..7
    const int tig  = lane & 3;              // 0..3
    const int qt    = blockIdx.x % QT_TILES;
    const int split = blockIdx.x / QT_TILES;

    const int q0 = qt * 128 + warp * 16 + g;
    const int q1 = q0 + 8;

    // A fragments straight from feats (scaled f32 -> bf16x2)
    const float sc = 0.25f * 1.4426950408889634f;
    const float2* f2 = reinterpret_cast<const float2*>(feats);
    float2 v00 = f2[q0 * 8 + tig];
    float2 v02 = f2[q0 * 8 + tig + 4];
    float2 v10 = f2[q1 * 8 + tig];
    float2 v12 = f2[q1 * 8 + tig + 4];
    const uint32_t a0 = bf2_u32(__floats2bfloat162_rn(v00.x * sc, v00.y * sc));
    const uint32_t a1 = bf2_u32(__floats2bfloat162_rn(v10.x * sc, v10.y * sc));
    const uint32_t a2 = bf2_u32(__floats2bfloat162_rn(v02.x * sc, v02.y * sc));
    const uint32_t a3 = bf2_u32(__floats2bfloat162_rn(v12.x * sc, v12.y * sc));

    float se0 = 0.0f, se1 = 0.0f, sw0 = 0.0f, sw1 = 0.0f;

    const int key0 = split * KEYS_PER_SPLIT;

    for (int tile = 0; tile < TILES; tile++) {
        __syncthreads();
        // stage 512 keys: src float4 f covers key f/2, half f&1 (32B/key)
        {
            const float4* src = reinterpret_cast<const float4*>(g_kb)
                              + (key0 + tile * KEYTILE) * 2;
            float4* dst = reinterpret_cast<float4*>(sk);
            #pragma unroll
            for (int f = tid; f < KEYTILE * 2; f += TPB) {
                int key = f >> 1, half = f & 1;
                dst[key * 3 + half] = src[f];
            }
        }
        __syncthreads();

        #pragma unroll 4
        for (int j = 0; j < KEYTILE / 8; j++) {
            const int kb = j * 8 + g;       // this thread's B-fragment key
            uint32_t b0 = sk[kb * 12 + tig];
            uint32_t b1 = sk[kb * 12 + tig + 4];

            float d0, d1, d2, d3;
            asm volatile(
                "mma.sync.aligned.m16n8k16.row.col.f32.bf16.bf16.f32 "
                "{%0,%1,%2,%3}, {%4,%5,%6,%7}, {%8,%9}, {%10,%11,%12,%13};"
                : "=f"(d0), "=f"(d1), "=f"(d2), "=f"(d3)
                : "r"(a0), "r"(a1), "r"(a2), "r"(a3), "r"(b0), "r"(b1),
                  "f"(0.0f), "f"(0.0f), "f"(0.0f), "f"(0.0f));

            // d0,d1: row g (keys 2tig,2tig+1); d2,d3: row g+8
            // hybrid exp: half MUFU, half fma-pipe, alternating by j parity
            float e0, e1, e2, e3;
            if (j & 1) {
                e0 = bexp2(d0);      e1 = bexp2(d1);
                e2 = ex2_approx(d2); e3 = ex2_approx(d3);
            } else {
                e0 = ex2_approx(d0); e1 = ex2_approx(d1);
                e2 = bexp2(d2);      e3 = bexp2(d3);
            }
            se0 += e0; sw0 = fmaf(e0, d0, sw0);
            se0 += e1; sw0 = fmaf(e1, d1, sw0);
            se1 += e2; sw1 = fmaf(e2, d2, sw1);
            se1 += e3; sw1 = fmaf(e3, d3, sw1);
        }
    }

    // reduce across the 4 threads of each row-quad (tids 4g..4g+3)
    se0 += __shfl_xor_sync(0xffffffffu, se0, 1);
    se0 += __shfl_xor_sync(0xffffffffu, se0, 2);
    se1 += __shfl_xor_sync(0xffffffffu, se1, 1);
    se1 += __shfl_xor_sync(0xffffffffu, se1, 2);
    sw0 += __shfl_xor_sync(0xffffffffu, sw0, 1);
    sw0 += __shfl_xor_sync(0xffffffffu, sw0, 2);
    sw1 += __shfl_xor_sync(0xffffffffu, sw1, 1);
    sw1 += __shfl_xor_sync(0xffffffffu, sw1, 2);

    if (tig == 0) {
        g_se[split][q0] = se0;
        g_sw[split][q0] = sw0;
        g_se[split][q1] = se1;
        g_sw[split][q1] = sw1;
    }
}

// ---------------------------------------------------------------------------
// Kernel 2: SOP (R15 version). 96 blocks x 128 points; 8 independent fmaf
// chains. w = sigmoid(4*ln2 * sw/se); M_b = sum_i w_i^2 f_i f_i^T. LAST
// block (atomic counter) reduces the 96 partials with 8-way MLP,
// L2-normalizes, writes the 256-float output, resets the counter.
// (topK=1 -> all points kept; /k cancels in the L2-normalize.)
// ---------------------------------------------------------------------------
__global__ void __launch_bounds__(256) sop_kernel(const float* __restrict__ feats,
                                                  float* __restrict__ out) {
    __shared__ float sf[SOP_BPTS][DIM];
    __shared__ float sw2[SOP_BPTS];
    __shared__ float red[256];
    __shared__ unsigned int isLast;

    const int tid = threadIdx.x;
    const int b   = blockIdx.x;

    // head: w^2 for this block's 128 points (threads 0..127)
    if (tid < SOP_BPTS) {
        const int p = b * SOP_BPTS + tid;
        float se = 0.0f, sw = 0.0f;
        #pragma unroll
        for (int s = 0; s < KSPLIT; s++) {
            se += g_se[s][p];
            sw += g_sw[s][p];
        }
        const float c4ln2 = 4.0f * 0.6931471805599453f;
        float cf = c4ln2 * sw / se;
        float w = 1.0f / (1.0f + __expf(-cf));
        sw2[tid] = w * w;
    }
    // feats for 128 points: 512 float4 loads, two per thread
    {
        const float4* src = reinterpret_cast<const float4*>(feats) + b * 512;
        #pragma unroll
        for (int k = 0; k < 2; k++) {
            int idx = tid + k * 256;
            float4 v = src[idx];
            reinterpret_cast<float4*>(&sf[idx >> 2][(idx & 3) * 4])[0] = v;
        }
    }
    __syncthreads();

    // thread t owns entry (d, e); 8 independent chains over the 128 points
    const int d = tid >> 4;
    const int e = tid & 15;
    float a0 = 0.f, a1 = 0.f, a2 = 0.f, a3 = 0.f;
    float a4 = 0.f, a5 = 0.f, a6 = 0.f, a7 = 0.f;
    #pragma unroll
    for (int i = 0; i < SOP_BPTS; i += 8) {
        a0 = fmaf(sw2[i + 0] * sf[i + 0][d], sf[i + 0][e], a0);
        a1 = fmaf(sw2[i + 1] * sf[i + 1][d], sf[i + 1][e], a1);
        a2 = fmaf(sw2[i + 2] * sf[i + 2][d], sf[i + 2][e], a2);
        a3 = fmaf(sw2[i + 3] * sf[i + 3][d], sf[i + 3][e], a3);
        a4 = fmaf(sw2[i + 4] * sf[i + 4][d], sf[i + 4][e], a4);
        a5 = fmaf(sw2[i + 5] * sf[i + 5][d], sf[i + 5][e], a5);
        a6 = fmaf(sw2[i + 6] * sf[i + 6][d], sf[i + 6][e], a6);
        a7 = fmaf(sw2[i + 7] * sf[i + 7][d], sf[i + 7][e], a7);
    }
    g_Mpart[b][tid] = ((a0 + a1) + (a2 + a3)) + ((a4 + a5) + (a6 + a7));

    // ---- last-block finalize (deterministic; counter self-resets) ----
    __threadfence();
    if (tid == 0) isLast = (atomicAdd(&g_cnt, 1u) == SOP_BLOCKS - 1) ? 1u : 0u;
    __syncthreads();
    if (isLast) {
        __threadfence();
        float v0 = 0.f, v1 = 0.f, v2 = 0.f, v3 = 0.f;
        float v4 = 0.f, v5 = 0.f, v6 = 0.f, v7 = 0.f;
        #pragma unroll
        for (int bb = 0; bb < SOP_BLOCKS; bb += 8) {
            v0 += g_Mpart[bb + 0][tid];
            v1 += g_Mpart[bb + 1][tid];
            v2 += g_Mpart[bb + 2][tid];
            v3 += g_Mpart[bb + 3][tid];
            v4 += g_Mpart[bb + 4][tid];
            v5 += g_Mpart[bb + 5][tid];
            v6 += g_Mpart[bb + 6][tid];
            v7 += g_Mpart[bb + 7][tid];
        }
        float v = ((v0 + v1) + (v2 + v3)) + ((v4 + v5) + (v6 + v7));

        red[tid] = v * v;
        __syncthreads();
        #pragma unroll
        for (int o = 128; o > 0; o >>= 1) {
            if (tid < o) red[tid] += red[tid + o];
            __syncthreads();
        }
        float inv = 1.0f / sqrtf(red[0]);
        out[tid] = v * inv;
        if (tid == 0) g_cnt = 0;
    }
}

// ---------------------------------------------------------------------------
extern "C" void kernel_launch(void* const* d_in, const int* in_sizes, int n_in,
                              void* d_out, int out_size) {
    const float* feats = (const float*)d_in[0];
    float* out = (float*)d_out;

    convert_kernel<<<NPTS * 4 / 256, 256>>>(feats);
    attn_mma_kernel<<<KSPLIT * QT_TILES, TPB>>>(feats);
    sop_kernel<<<SOP_BLOCKS, 256>>>(feats, out);
}

// round 17
// speedup vs baseline: 1.1955x; 1.1955x over previous
#include <cuda_runtime.h>
#include <cuda_bf16.h>
#include <cstdint>

#define NPTS 12288
#define DIM 16
#define KSPLIT 6
#define QT_TILES 96                     // 12288/128 query tiles
#define TPB 256
#define KEYS_PER_SPLIT (NPTS / KSPLIT)  // 2048
#define KEYTILE 512
#define TILES (KEYS_PER_SPLIT / KEYTILE)// 4

// ---- scratch (__device__ globals; no allocation allowed) ------------------
__device__ uint32_t g_kb[NPTS * 8];         // keys, bf16x2, unscaled
__device__ float g_se[KSPLIT][NPTS];        // exp-sum partials
__device__ float g_sw[KSPLIT][NPTS];        // exp*score-sum partials (log2-units)
__device__ float g_Mpart[QT_TILES][256];    // per-tile SOP partials
__device__ unsigned int g_tilecnt[QT_TILES];// per-tile split counters (self-reset)
__device__ unsigned int g_cnt = 0;          // tile-done counter (self-reset)

__device__ __forceinline__ float ex2_approx(float x) {
    float r; asm("ex2.approx.ftz.f32 %0, %1;" : "=f"(r) : "f"(x)); return r;
}
__device__ __forceinline__ uint32_t bf2_u32(__nv_bfloat162 v) {
    return *reinterpret_cast<uint32_t*>(&v);
}

// ---------------------------------------------------------------------------
// Kernel 0: convert feats (f32) to the bf16 KEY array only (queries are
// converted in-kernel by attn). One float4 -> one uint2 per thread.
// ---------------------------------------------------------------------------
__global__ void convert_kernel(const float* __restrict__ feats) {
    const int i = blockIdx.x * 256 + threadIdx.x;   // float4 index, 0..49151
    float4 v = reinterpret_cast<const float4*>(feats)[i];
    uint2 kb = make_uint2(bf2_u32(__floats2bfloat162_rn(v.x, v.y)),
                          bf2_u32(__floats2bfloat162_rn(v.z, v.w)));
    reinterpret_cast<uint2*>(g_kb)[i] = kb;
}

// ---------------------------------------------------------------------------
// Kernel 1: tensor-core attention row stats (R15 mainloop, proven 27.6us)
// PLUS fused SOP tail. After a block stores its split's se/sw, it bumps
// g_tilecnt[qt]; the LAST split-block for tile qt computes w^2 + the 128-pt
// SOP partial for that tile (overlapped with still-running blocks), and the
// last tile overall does the 96-partial reduce + L2-normalize + output.
// All counters self-reset -> graph-replay safe; fixed reduce order ->
// deterministic. Identity: <ctx_q,f_q> = 4*ln2 * sw_q/se_q.
// ---------------------------------------------------------------------------
__global__ void __launch_bounds__(TPB, 4) attn_mma_kernel(const float* __restrict__ feats,
                                                          float* __restrict__ out) {
    __shared__ __align__(16) uint32_t sk[KEYTILE * 12];   // 24 KB key tile; reused by tail
    __shared__ unsigned int isLastTile, isLastAll;

    const int tid  = threadIdx.x;
    const int warp = tid >> 5;
    const int lane = tid & 31;
    const int g    = lane >> 2;             // 0..7
    const int tig  = lane & 3;              // 0..3
    const int qt    = blockIdx.x % QT_TILES;
    const int split = blockIdx.x / QT_TILES;

    const int q0 = qt * 128 + warp * 16 + g;
    const int q1 = q0 + 8;

    // A fragments straight from feats (scaled f32 -> bf16x2)
    const float sc = 0.25f * 1.4426950408889634f;
    const float2* f2 = reinterpret_cast<const float2*>(feats);
    float2 v00 = f2[q0 * 8 + tig];
    float2 v02 = f2[q0 * 8 + tig + 4];
    float2 v10 = f2[q1 * 8 + tig];
    float2 v12 = f2[q1 * 8 + tig + 4];
    const uint32_t a0 = bf2_u32(__floats2bfloat162_rn(v00.x * sc, v00.y * sc));
    const uint32_t a1 = bf2_u32(__floats2bfloat162_rn(v10.x * sc, v10.y * sc));
    const uint32_t a2 = bf2_u32(__floats2bfloat162_rn(v02.x * sc, v02.y * sc));
    const uint32_t a3 = bf2_u32(__floats2bfloat162_rn(v12.x * sc, v12.y * sc));

    float se0 = 0.0f, se1 = 0.0f, sw0 = 0.0f, sw1 = 0.0f;

    const int key0 = split * KEYS_PER_SPLIT;

    for (int tile = 0; tile < TILES; tile++) {
        __syncthreads();
        // stage 512 keys: src float4 f covers key f/2, half f&1 (32B/key)
        {
            const float4* src = reinterpret_cast<const float4*>(g_kb)
                              + (key0 + tile * KEYTILE) * 2;
            float4* dst = reinterpret_cast<float4*>(sk);
            #pragma unroll
            for (int f = tid; f < KEYTILE * 2; f += TPB) {
                int key = f >> 1, half = f & 1;
                dst[key * 3 + half] = src[f];
            }
        }
        __syncthreads();

        #pragma unroll 4
        for (int j = 0; j < KEYTILE / 8; j++) {
            const int kb = j * 8 + g;       // this thread's B-fragment key
            uint32_t b0 = sk[kb * 12 + tig];
            uint32_t b1 = sk[kb * 12 + tig + 4];

            float d0, d1, d2, d3;
            asm volatile(
                "mma.sync.aligned.m16n8k16.row.col.f32.bf16.bf16.f32 "
                "{%0,%1,%2,%3}, {%4,%5,%6,%7}, {%8,%9}, {%10,%11,%12,%13};"
                : "=f"(d0), "=f"(d1), "=f"(d2), "=f"(d3)
                : "r"(a0), "r"(a1), "r"(a2), "r"(a3), "r"(b0), "r"(b1),
                  "f"(0.0f), "f"(0.0f), "f"(0.0f), "f"(0.0f));

            // d0,d1: row g (keys 2tig,2tig+1); d2,d3: row g+8
            float e;
            e = ex2_approx(d0); se0 += e; sw0 = fmaf(e, d0, sw0);
            e = ex2_approx(d1); se0 += e; sw0 = fmaf(e, d1, sw0);
            e = ex2_approx(d2); se1 += e; sw1 = fmaf(e, d2, sw1);
            e = ex2_approx(d3); se1 += e; sw1 = fmaf(e, d3, sw1);
        }
    }

    // reduce across the 4 threads of each row-quad (tids 4g..4g+3)
    se0 += __shfl_xor_sync(0xffffffffu, se0, 1);
    se0 += __shfl_xor_sync(0xffffffffu, se0, 2);
    se1 += __shfl_xor_sync(0xffffffffu, se1, 1);
    se1 += __shfl_xor_sync(0xffffffffu, se1, 2);
    sw0 += __shfl_xor_sync(0xffffffffu, sw0, 1);
    sw0 += __shfl_xor_sync(0xffffffffu, sw0, 2);
    sw1 += __shfl_xor_sync(0xffffffffu, sw1, 1);
    sw1 += __shfl_xor_sync(0xffffffffu, sw1, 2);

    if (tig == 0) {
        g_se[split][q0] = se0;
        g_sw[split][q0] = sw0;
        g_se[split][q1] = se1;
        g_sw[split][q1] = sw1;
    }

    // ================= fused SOP tail =================
    __threadfence();
    __syncthreads();
    if (tid == 0)
        isLastTile = (atomicAdd(&g_tilecnt[qt], 1u) == KSPLIT - 1) ? 1u : 0u;
    __syncthreads();
    if (!isLastTile) return;

    // This block is the last split for tile qt: all 6 splits' se/sw for
    // points qt*128..qt*128+127 are visible (fence + atomic order).
    __threadfence();

    // reuse sk smem: sf[128][16] floats, sw2[128], red[256]
    float* sf  = reinterpret_cast<float*>(sk);
    float* sw2 = sf + 128 * DIM;
    float* red = sw2 + 128;

    if (tid < 128) {
        const int p = qt * 128 + tid;
        float se = 0.0f, sw = 0.0f;
        #pragma unroll
        for (int s = 0; s < KSPLIT; s++) {
            se += g_se[s][p];
            sw += g_sw[s][p];
        }
        const float c4ln2 = 4.0f * 0.6931471805599453f;
        float cf = c4ln2 * sw / se;
        float w = 1.0f / (1.0f + __expf(-cf));
        sw2[tid] = w * w;
    }
    // feats for the tile's 128 points: 512 float4, two per thread
    {
        const float4* src = reinterpret_cast<const float4*>(feats) + qt * 512;
        #pragma unroll
        for (int k = 0; k < 2; k++) {
            int idx = tid + k * 256;          // float4 index; 4 per point
            float4 v = src[idx];
            reinterpret_cast<float4*>(&sf[(idx >> 2) * DIM + (idx & 3) * 4])[0] = v;
        }
    }
    __syncthreads();

    // thread owns entry (d, e); 8 independent chains over 128 points
    const int d = tid >> 4;
    const int e = tid & 15;
    float p0 = 0.f, p1 = 0.f, p2 = 0.f, p3 = 0.f;
    float p4 = 0.f, p5 = 0.f, p6 = 0.f, p7 = 0.f;
    #pragma unroll
    for (int i = 0; i < 128; i += 8) {
        p0 = fmaf(sw2[i + 0] * sf[(i + 0) * DIM + d], sf[(i + 0) * DIM + e], p0);
        p1 = fmaf(sw2[i + 1] * sf[(i + 1) * DIM + d], sf[(i + 1) * DIM + e], p1);
        p2 = fmaf(sw2[i + 2] * sf[(i + 2) * DIM + d], sf[(i + 2) * DIM + e], p2);
        p3 = fmaf(sw2[i + 3] * sf[(i + 3) * DIM + d], sf[(i + 3) * DIM + e], p3);
        p4 = fmaf(sw2[i + 4] * sf[(i + 4) * DIM + d], sf[(i + 4) * DIM + e], p4);
        p5 = fmaf(sw2[i + 5] * sf[(i + 5) * DIM + d], sf[(i + 5) * DIM + e], p5);
        p6 = fmaf(sw2[i + 6] * sf[(i + 6) * DIM + d], sf[(i + 6) * DIM + e], p6);
        p7 = fmaf(sw2[i + 7] * sf[(i + 7) * DIM + d], sf[(i + 7) * DIM + e], p7);
    }
    g_Mpart[qt][tid] = ((p0 + p1) + (p2 + p3)) + ((p4 + p5) + (p6 + p7));

    if (tid == 0) g_tilecnt[qt] = 0;          // self-reset for graph replay

    // ---- global finalize by the last tile overall ----
    __threadfence();
    __syncthreads();
    if (tid == 0)
        isLastAll = (atomicAdd(&g_cnt, 1u) == QT_TILES - 1) ? 1u : 0u;
    __syncthreads();
    if (!isLastAll) return;

    __threadfence();
    float v0 = 0.f, v1 = 0.f, v2 = 0.f, v3 = 0.f;
    float v4 = 0.f, v5 = 0.f, v6 = 0.f, v7 = 0.f;
    #pragma unroll
    for (int bb = 0; bb < QT_TILES; bb += 8) {
        v0 += g_Mpart[bb + 0][tid];
        v1 += g_Mpart[bb + 1][tid];
        v2 += g_Mpart[bb + 2][tid];
        v3 += g_Mpart[bb + 3][tid];
        v4 += g_Mpart[bb + 4][tid];
        v5 += g_Mpart[bb + 5][tid];
        v6 += g_Mpart[bb + 6][tid];
        v7 += g_Mpart[bb + 7][tid];
    }
    float v = ((v0 + v1) + (v2 + v3)) + ((v4 + v5) + (v6 + v7));

    red[tid] = v * v;
    __syncthreads();
    #pragma unroll
    for (int o = 128; o > 0; o >>= 1) {
        if (tid < o) red[tid] += red[tid + o];
        __syncthreads();
    }
    float inv = 1.0f / sqrtf(red[0]);
    out[tid] = v * inv;
    if (tid == 0) g_cnt = 0;                  // self-reset for graph replay
}

// ---------------------------------------------------------------------------
extern "C" void kernel_launch(void* const* d_in, const int* in_sizes, int n_in,
                              void* d_out, int out_size) {
    const float* feats = (const float*)d_in[0];
    float* out = (float*)d_out;

    convert_kernel<<<NPTS * 4 / 256, 256>>>(feats);
    attn_mma_kernel<<<KSPLIT * QT_TILES, TPB>>>(feats, out);
}